// round 5
// baseline (speedup 1.0000x reference)
#include <cuda_runtime.h>
#include <math.h>

// Problem constants
#define BB   32        // batch
#define TT   512       // time steps
#define DD   512       // input dim
#define HH   512       // hidden dim
#define G4   2048      // 4*H
#define NLAYER 2
#define NBLK 128       // recurrent grid size

// ---------------- scratch (device globals; no allocation allowed) ----------
__device__ float d_gx[(size_t)TT * BB * G4];   // [T][B][4H] pre-activations (reused per layer)
__device__ float d_y0[(size_t)TT * BB * HH];   // [T][B][H] layer-0 outputs
__device__ float d_hbuf[2][BB * HH];           // ping-pong hidden state
__device__ unsigned int d_bar_count;           // monotonic arrival counter (zeroed by gemm)

// ---------------- packed fp32x2 helpers (sm_100+) ---------------------------
__device__ __forceinline__ unsigned long long fma2(unsigned long long a,
                                                   unsigned long long b,
                                                   unsigned long long c) {
    unsigned long long d;
    asm("fma.rn.f32x2 %0, %1, %2, %3;" : "=l"(d) : "l"(a), "l"(b), "l"(c));
    return d;
}
__device__ __forceinline__ float2 unpack2(unsigned long long v) {
    float2 f;
    asm("mov.b64 {%0, %1}, %2;" : "=f"(f.x), "=f"(f.y) : "l"(v));
    return f;
}

// ---------------- fast activations -----------------------------------------
__device__ __forceinline__ float fast_tanh(float x) {
    float y;
    asm("tanh.approx.f32 %0, %1;" : "=f"(y) : "f"(x));
    return y;
}
__device__ __forceinline__ float fast_sigmoid(float x) {
    return 0.5f + 0.5f * fast_tanh(0.5f * x);
}

// ---------------- grid-wide barrier (all blocks co-resident) ---------------
// Monotonic counter: arrival = red.release (no-return REDG), wait = spin on
// ld.acquire until count >= iter*NBLK. Counter is zeroed by the preceding
// gemm launch (stream order). 128 blocks x 107KB smem -> guaranteed wave-1
// residency on 148 SMs: deadlock-free.
__device__ __forceinline__ void grid_barrier(unsigned int target) {
    __syncthreads();
    if (threadIdx.x == 0) {
        asm volatile("red.release.gpu.global.add.u32 [%0], 1;"
                     :: "l"(&d_bar_count) : "memory");
        unsigned int v;
        do {
            asm volatile("ld.acquire.gpu.global.u32 %0, [%1];"
                         : "=r"(v) : "l"(&d_bar_count));
        } while (v < target);
    }
    __syncthreads();
}

// ---------------- big GEMM: gx = A @ Wih^T + (bih+bhh) ---------------------
// M=16384 (rows m = t*B + b), N=2048, K=512. fp32x2: rows paired along M.
// MODE 0: A = x [B][T][D] (row offset (b*T+t)*D). MODE 1: A = d_y0 (offset m*H).
template <int MODE>
__global__ __launch_bounds__(256) void gemm_gx(const float* __restrict__ A,
                                               const float* __restrict__ W,
                                               const float* __restrict__ bih,
                                               const float* __restrict__ bhh) {
    __shared__ float As[8][132];
    __shared__ float Bs[8][264];    // value-replicated pairs: Bs[k][2n]=Bs[k][2n+1]=b_n

    const int tid = threadIdx.x;
    const int m0 = blockIdx.y * 128;
    const int n0 = blockIdx.x * 128;

    // reset the recurrent barrier counter for the following lstm_rec launch
    if (blockIdx.x == 0 && blockIdx.y == 0 && tid == 0) d_bar_count = 0u;

    const int lr = tid >> 1;         // 0..127: row within tile
    const int lk = (tid & 1) * 4;    // 0 or 4: k offset within 8-wide tile

    const float* Abase = (MODE == 0) ? A : d_y0;
    size_t aoff;
    {
        int m = m0 + lr;
        if (MODE == 0) {
            int t = m >> 5;          // m / 32  (B == 32)
            int b = m & 31;
            aoff = ((size_t)b * TT + t) * DD;
        } else {
            aoff = (size_t)m * HH;
        }
    }
    const float4* Aload = (const float4*)(Abase + aoff);
    const float4* Wload = (const float4*)(W + (size_t)(n0 + lr) * 512);

    const int tx = tid & 15;
    const int ty = tid >> 4;

    // acc2[i2][j]: i2 = row-pair (2 rows per u64), j = 8 cols
    unsigned long long acc2[4][8];
#pragma unroll
    for (int i = 0; i < 4; ++i)
#pragma unroll
        for (int j = 0; j < 8; ++j) acc2[i][j] = 0ull;

    // prefetch tile 0
    float4 ar = Aload[lk >> 2];
    float4 wr = Wload[lk >> 2];

    for (int kt = 0; kt < 64; ++kt) {
        __syncthreads();
        As[lk + 0][lr] = ar.x; As[lk + 1][lr] = ar.y;
        As[lk + 2][lr] = ar.z; As[lk + 3][lr] = ar.w;
        *(float2*)&Bs[lk + 0][2 * lr] = make_float2(wr.x, wr.x);
        *(float2*)&Bs[lk + 1][2 * lr] = make_float2(wr.y, wr.y);
        *(float2*)&Bs[lk + 2][2 * lr] = make_float2(wr.z, wr.z);
        *(float2*)&Bs[lk + 3][2 * lr] = make_float2(wr.w, wr.w);
        __syncthreads();
        if (kt < 63) {   // prefetch next tile while computing this one
            ar = Aload[(kt + 1) * 2 + (lk >> 2)];
            wr = Wload[(kt + 1) * 2 + (lk >> 2)];
        }
#pragma unroll
        for (int k = 0; k < 8; ++k) {
            const ulonglong2 aLo = *(const ulonglong2*)&As[k][ty * 4];      // rows +0/1, +2/3
            const ulonglong2 aHi = *(const ulonglong2*)&As[k][64 + ty * 4]; // rows 64+..
            const ulonglong2 b01 = *(const ulonglong2*)&Bs[k][8 * tx];
            const ulonglong2 b23 = *(const ulonglong2*)&Bs[k][8 * tx + 4];
            const ulonglong2 b45 = *(const ulonglong2*)&Bs[k][128 + 8 * tx];
            const ulonglong2 b67 = *(const ulonglong2*)&Bs[k][128 + 8 * tx + 4];
            const unsigned long long av[4] = {aLo.x, aLo.y, aHi.x, aHi.y};
            const unsigned long long bv[8] = {b01.x, b01.y, b23.x, b23.y,
                                              b45.x, b45.y, b67.x, b67.y};
#pragma unroll
            for (int i = 0; i < 4; ++i)
#pragma unroll
                for (int j = 0; j < 8; ++j)
                    acc2[i][j] = fma2(av[i], bv[j], acc2[i][j]);
        }
    }

    // bias + store
    float bias[8];
#pragma unroll
    for (int j = 0; j < 8; ++j) {
        int nn = n0 + ((j < 4) ? (tx * 4 + j) : (64 + tx * 4 + j - 4));
        bias[j] = bih[nn] + bhh[nn];
    }
#pragma unroll
    for (int i2 = 0; i2 < 4; ++i2) {
        const int mrow0 = (i2 < 2) ? (m0 + ty * 4 + 2 * i2)
                                   : (m0 + 64 + ty * 4 + 2 * (i2 - 2));
        float r0[8], r1[8];
#pragma unroll
        for (int j = 0; j < 8; ++j) {
            const float2 v = unpack2(acc2[i2][j]);
            r0[j] = v.x + bias[j];
            r1[j] = v.y + bias[j];
        }
        float* g0 = &d_gx[(size_t)mrow0 * G4 + n0];
        float* g1 = &d_gx[(size_t)(mrow0 + 1) * G4 + n0];
        *(float4*)&g0[tx * 4]      = make_float4(r0[0], r0[1], r0[2], r0[3]);
        *(float4*)&g0[64 + tx * 4] = make_float4(r0[4], r0[5], r0[6], r0[7]);
        *(float4*)&g1[tx * 4]      = make_float4(r1[0], r1[1], r1[2], r1[3]);
        *(float4*)&g1[64 + tx * 4] = make_float4(r1[4], r1[5], r1[6], r1[7]);
    }
}

// ---------------- persistent recurrent kernel ------------------------------
// 128 blocks x 256 threads. Block owns hidden units [blockIdx.x*4, +4) => 16
// Whh rows (4 units x 4 gates) held in shared for ALL 512 steps.
// Warp w: row-group rg=w&1 (8 rows), K-chunk ks=w>>1 (128 k each).
// lane = batch. Dot products use packed fma.f32x2 (pairs along k).
#define SMEM_W   (16 * 512)        // 8192 floats
#define SMEM_H   (32 * 516)        // padded h, 16512 floats
#define SMEM_P   (4 * 512)         // partials [ks][batch][16], 2048 floats
#define SMEM_REC_FLOATS (SMEM_W + SMEM_H + SMEM_P)
#define SMEM_REC_BYTES  (SMEM_REC_FLOATS * 4)

__global__ void lstm_rec(const float* __restrict__ Whh,   // layer's [2048][512]
                         int store_y,
                         float* __restrict__ out_h,       // [B][H] slice of d_out
                         float* __restrict__ out_c) {
    extern __shared__ float sm[];
    float* Wsh = sm;                    // [16][512]
    float* hsh = sm + SMEM_W;           // [32][516]
    float* psh = hsh + SMEM_H;          // [4][32][16]

    const int tid  = threadIdx.x;
    const int warp = tid >> 5;
    const int lane = tid & 31;
    const int hidx0 = blockIdx.x * 4;

    // load the 16 Whh rows this block owns (reused for all 512 steps)
    for (int idx = tid; idx < 16 * 512; idx += 256) {
        int j = idx >> 9, k = idx & 511;
        int gate = j & 3, hl = j >> 2;
        Wsh[idx] = Whh[(size_t)(gate * HH + hidx0 + hl) * HH + k];
    }

    const int rg = warp & 1;        // row group (rows rg*8 .. rg*8+7)
    const int ks = warp >> 1;       // k-split 0..3
    const int kbase = ks * 128;

    float c_reg = 0.f;              // cell state (threads 0..127)
    const int ab  = tid >> 2;       // batch for activation
    const int ahl = tid & 3;        // local hidden unit for activation
    const int hid = hidx0 + ahl;
    const float* gxbase = d_gx + (size_t)ab * G4 + hid;   // advance by B*G4 per t

    __syncthreads();

    for (int t = 0; t < TT; ++t) {
        // ---- prefetch gate pre-activations (independent of h; latency
        //      hidden under h-staging + dot-product loop) ----
        float gxi, gxf, gxg, gxo;
        if (tid < 128) {
            const float* gxp = gxbase + (size_t)t * (BB * G4);
            gxi = __ldcs(gxp + 0 * HH);
            gxf = __ldcs(gxp + 1 * HH);
            gxg = __ldcs(gxp + 2 * HH);
            gxo = __ldcs(gxp + 3 * HH);
        }

        // ---- stage h_t into shared ----
        if (t == 0) {
            for (int i = tid; i < SMEM_H; i += 256) hsh[i] = 0.f;
        } else {
            const float4* hb = (const float4*)&d_hbuf[t & 1][0];
            for (int i = tid; i < 4096; i += 256) {
                float4 v = __ldcg(hb + i);                       // bypass stale L1
                *(float4*)&hsh[(i >> 7) * 516 + (i & 127) * 4] = v;
            }
        }
        __syncthreads();

        // ---- packed dot products:
        //      acc2[r] accumulates k-pairs; horizontal add at the end.
        unsigned long long acc2[8];
#pragma unroll
        for (int r = 0; r < 8; ++r) acc2[r] = 0ull;
        const ulonglong2* hrow2 = (const ulonglong2*)&hsh[lane * 516 + kbase];
#pragma unroll 4
        for (int kk = 0; kk < 32; ++kk) {
            const ulonglong2 hv = hrow2[kk];
#pragma unroll
            for (int r = 0; r < 8; ++r) {
                const ulonglong2 wv =
                    *(const ulonglong2*)&Wsh[(rg * 8 + r) * 512 + kbase + kk * 4];
                acc2[r] = fma2(hv.x, wv.x, acc2[r]);
                acc2[r] = fma2(hv.y, wv.y, acc2[r]);
            }
        }
#pragma unroll
        for (int r = 0; r < 8; ++r) {
            const float2 f = unpack2(acc2[r]);
            psh[ks * 512 + lane * 16 + rg * 8 + r] = f.x + f.y;
        }
        __syncthreads();

        // ---- activation (threads 0..127: one (batch, unit) each) ----
        if (tid < 128) {
            float4 p = *(const float4*)&psh[ab * 16 + ahl * 4];
#pragma unroll
            for (int q = 1; q < 4; ++q) {
                const float4 v = *(const float4*)&psh[q * 512 + ab * 16 + ahl * 4];
                p.x += v.x; p.y += v.y; p.z += v.z; p.w += v.w;
            }
            p.x += gxi;   // i
            p.y += gxf;   // f
            p.z += gxg;   // g
            p.w += gxo;   // o
            const float ig = fast_sigmoid(p.x);
            const float fg = fast_sigmoid(p.y);
            const float gg = fast_tanh(p.z);
            const float og = fast_sigmoid(p.w);
            c_reg = fg * c_reg + ig * gg;
            const float h = og * fast_tanh(c_reg);
            __stcg(&d_hbuf[(t + 1) & 1][ab * HH + hid], h);
            if (store_y) __stcs(&d_y0[((size_t)t * BB + ab) * HH + hid], h);
            if (t == TT - 1) {
                out_h[ab * HH + hid] = h;
                out_c[ab * HH + hid] = c_reg;
            }
        }
        if (t != TT - 1) grid_barrier((unsigned int)(t + 1) * NBLK);
    }
}

// ---------------- launch ----------------------------------------------------
extern "C" void kernel_launch(void* const* d_in, const int* in_sizes, int n_in,
                              void* d_out, int out_size) {
    (void)in_sizes; (void)n_in; (void)out_size;
    const float* x    = (const float*)d_in[0];   // [32][512][512]
    const float* W_ih = (const float*)d_in[1];   // [2][2048][512]
    const float* W_hh = (const float*)d_in[2];   // [2][2048][512]
    const float* b_ih = (const float*)d_in[3];   // [2][2048]
    const float* b_hh = (const float*)d_in[4];   // [2][2048]
    float* out = (float*)d_out;                  // h_n [2][32][512] then c_n [2][32][512]

    cudaFuncSetAttribute(lstm_rec, cudaFuncAttributeMaxDynamicSharedMemorySize,
                         SMEM_REC_BYTES);

    const dim3 ggrid(16, 128);   // N tiles x M tiles
    const size_t wstride = (size_t)G4 * HH;      // per-layer weight stride
    const int LBH = NLAYER * BB * HH;            // 32768: offset of c_n block

    // layer 0
    gemm_gx<0><<<ggrid, 256>>>(x, W_ih, b_ih, b_hh);
    lstm_rec<<<NBLK, 256, SMEM_REC_BYTES>>>(W_hh, 1,
                                            out + 0 * BB * HH,
                                            out + LBH + 0 * BB * HH);
    // layer 1 (input = d_y0, consumed inside gemm_gx<1>)
    gemm_gx<1><<<ggrid, 256>>>(nullptr, W_ih + wstride, b_ih + G4, b_hh + G4);
    lstm_rec<<<NBLK, 256, SMEM_REC_BYTES>>>(W_hh + wstride, 0,
                                            out + 1 * BB * HH,
                                            out + LBH + 1 * BB * HH);
}

// round 12
// speedup vs baseline: 1.1485x; 1.1485x over previous
#include <cuda_runtime.h>
#include <math.h>

// Problem constants
#define BB   32        // batch
#define TT   512       // time steps
#define DD   512       // input dim
#define HH   512       // hidden dim
#define G4   2048      // 4*H
#define NLAYER 2
#define NBLK 128       // recurrent grid size

// ---------------- scratch (device globals; no allocation allowed) ----------
__device__ float d_gx[(size_t)TT * BB * G4];   // [T][B][4H] pre-activations (reused per layer)
__device__ float d_y0[(size_t)TT * BB * HH];   // [T][B][H] layer-0 outputs
__device__ float d_hbuf[2][BB * HH];           // ping-pong hidden state
__device__ unsigned int d_bar_count;           // monotonic arrival counter (zeroed by gemm)

// ---------------- fast activations -----------------------------------------
__device__ __forceinline__ float fast_tanh(float x) {
    float y;
    asm("tanh.approx.f32 %0, %1;" : "=f"(y) : "f"(x));
    return y;
}
__device__ __forceinline__ float fast_sigmoid(float x) {
    return 0.5f + 0.5f * fast_tanh(0.5f * x);
}

// ---------------- grid-wide barrier (all blocks co-resident) ---------------
// Monotonic counter: arrival = red.release (no-return REDG), wait = spin on
// ld.acquire until count >= iter*NBLK. Counter is zeroed by the preceding
// gemm launch (stream order). 128 blocks x ~107KB smem -> guaranteed wave-1
// residency on 148 SMs: deadlock-free.
__device__ __forceinline__ void grid_barrier(unsigned int target) {
    __syncthreads();
    if (threadIdx.x == 0) {
        asm volatile("red.release.gpu.global.add.u32 [%0], 1;"
                     :: "l"(&d_bar_count) : "memory");
        unsigned int v;
        do {
            asm volatile("ld.acquire.gpu.global.u32 %0, [%1];"
                         : "=r"(v) : "l"(&d_bar_count));
        } while (v < target);
    }
    __syncthreads();
}

// ---------------- big GEMM: gx = A @ Wih^T + (bih+bhh) ---------------------
// M=16384 (rows m = t*B + b), N=2048, K=512.  (R4 scalar-FFMA version)
// MODE 0: A = x [B][T][D] (row offset (b*T+t)*D). MODE 1: A = d_y0 (offset m*H).
template <int MODE>
__global__ __launch_bounds__(256) void gemm_gx(const float* __restrict__ A,
                                               const float* __restrict__ W,
                                               const float* __restrict__ bih,
                                               const float* __restrict__ bhh) {
    __shared__ float As[8][132];
    __shared__ float Bs[8][132];

    const int tid = threadIdx.x;
    const int m0 = blockIdx.y * 128;
    const int n0 = blockIdx.x * 128;

    // reset the recurrent barrier counter for the following lstm_rec launch
    if (blockIdx.x == 0 && blockIdx.y == 0 && tid == 0) d_bar_count = 0u;

    const int lr = tid >> 1;         // 0..127: row within tile
    const int lk = (tid & 1) * 4;    // 0 or 4: k offset within 8-wide tile

    const float* Abase = (MODE == 0) ? A : d_y0;
    size_t aoff;
    {
        int m = m0 + lr;
        if (MODE == 0) {
            int t = m >> 5;          // m / 32  (B == 32)
            int b = m & 31;
            aoff = ((size_t)b * TT + t) * DD;
        } else {
            aoff = (size_t)m * HH;
        }
    }
    const float4* Aload = (const float4*)(Abase + aoff);
    const float4* Wload = (const float4*)(W + (size_t)(n0 + lr) * 512);

    const int tx = tid & 15;
    const int ty = tid >> 4;

    float acc[8][8];
#pragma unroll
    for (int i = 0; i < 8; ++i)
#pragma unroll
        for (int j = 0; j < 8; ++j) acc[i][j] = 0.f;

    // prefetch tile 0
    float4 ar = Aload[lk >> 2];
    float4 wr = Wload[lk >> 2];

    for (int kt = 0; kt < 64; ++kt) {
        __syncthreads();
        As[lk + 0][lr] = ar.x; As[lk + 1][lr] = ar.y;
        As[lk + 2][lr] = ar.z; As[lk + 3][lr] = ar.w;
        Bs[lk + 0][lr] = wr.x; Bs[lk + 1][lr] = wr.y;
        Bs[lk + 2][lr] = wr.z; Bs[lk + 3][lr] = wr.w;
        __syncthreads();
        if (kt < 63) {   // prefetch next tile while computing this one
            ar = Aload[(kt + 1) * 2 + (lk >> 2)];
            wr = Wload[(kt + 1) * 2 + (lk >> 2)];
        }
#pragma unroll
        for (int k = 0; k < 8; ++k) {
            const float4 a0 = *(const float4*)(&As[k][ty * 4]);
            const float4 a1 = *(const float4*)(&As[k][64 + ty * 4]);
            const float4 b0 = *(const float4*)(&Bs[k][tx * 4]);
            const float4 b1 = *(const float4*)(&Bs[k][64 + tx * 4]);
            const float av[8] = {a0.x, a0.y, a0.z, a0.w, a1.x, a1.y, a1.z, a1.w};
            const float bv[8] = {b0.x, b0.y, b0.z, b0.w, b1.x, b1.y, b1.z, b1.w};
#pragma unroll
            for (int i = 0; i < 8; ++i)
#pragma unroll
                for (int j = 0; j < 8; ++j)
                    acc[i][j] = fmaf(av[i], bv[j], acc[i][j]);
        }
    }

    // bias + store
    float bias[8];
#pragma unroll
    for (int j = 0; j < 8; ++j) {
        int nn = n0 + ((j < 4) ? (tx * 4 + j) : (64 + tx * 4 + j - 4));
        bias[j] = bih[nn] + bhh[nn];
    }
#pragma unroll
    for (int i = 0; i < 8; ++i) {
        int mrow = m0 + ((i < 4) ? (ty * 4 + i) : (64 + ty * 4 + i - 4));
        float4 o0, o1;
        o0.x = acc[i][0] + bias[0]; o0.y = acc[i][1] + bias[1];
        o0.z = acc[i][2] + bias[2]; o0.w = acc[i][3] + bias[3];
        o1.x = acc[i][4] + bias[4]; o1.y = acc[i][5] + bias[5];
        o1.z = acc[i][6] + bias[6]; o1.w = acc[i][7] + bias[7];
        *(float4*)&d_gx[(size_t)mrow * G4 + n0 + tx * 4]      = o0;
        *(float4*)&d_gx[(size_t)mrow * G4 + n0 + 64 + tx * 4] = o1;
    }
}

// ---------------- persistent recurrent kernel ------------------------------
// 128 blocks x 256 threads. Block owns hidden units [blockIdx.x*4, +4) => 16
// Whh rows (4 units x 4 gates) held in shared for ALL 512 steps.
// Warp w: row-group rg=w&1 (8 rows), K-chunk ks=w>>1 (128 k each).
// lane = batch. Activation done by threads 0..127 (one per (batch, unit)).
//
// psh layout: [ks][lane][row] with lane stride 17 words ->
//   writes: 8 STS.32/warp, lanes stride 17 (odd) -> conflict-free.
//   act reads: 16 scalar LDS, <=2-way conflicts. (Old [ks][lane*16+row]
//   layout had 16-way conflicted writes: ~1000 crossbar cyc/step.)
#define PSTRIDE 17
#define SMEM_W   (16 * 512)           // 8192 floats
#define SMEM_H   (32 * 516)           // padded h, 16512 floats
#define SMEM_P   (4 * 32 * PSTRIDE)   // 2176 floats
#define SMEM_REC_FLOATS (SMEM_W + SMEM_H + SMEM_P)
#define SMEM_REC_BYTES  (SMEM_REC_FLOATS * 4)

__global__ void lstm_rec(const float* __restrict__ Whh,   // layer's [2048][512]
                         int store_y,
                         float* __restrict__ out_h,       // [B][H] slice of d_out
                         float* __restrict__ out_c) {
    extern __shared__ float sm[];
    float* Wsh = sm;                    // [16][512]
    float* hsh = sm + SMEM_W;           // [32][516]
    float* psh = hsh + SMEM_H;          // [4][32][17]

    const int tid  = threadIdx.x;
    const int warp = tid >> 5;
    const int lane = tid & 31;
    const int hidx0 = blockIdx.x * 4;

    // load the 16 Whh rows this block owns (reused for all 512 steps)
    for (int idx = tid; idx < 16 * 512; idx += 256) {
        int j = idx >> 9, k = idx & 511;
        int gate = j & 3, hl = j >> 2;
        Wsh[idx] = Whh[(size_t)(gate * HH + hidx0 + hl) * HH + k];
    }

    const int rg = warp & 1;        // row group (rows rg*8 .. rg*8+7)
    const int ks = warp >> 1;       // k-split 0..3
    const int kbase = ks * 128;

    float c_reg = 0.f;              // cell state (threads 0..127)
    const int ab  = tid >> 2;       // batch for activation
    const int ahl = tid & 3;        // local hidden unit for activation
    const int hid = hidx0 + ahl;
    const float* gxbase = d_gx + (size_t)ab * G4 + hid;   // advance by B*G4 per t

    __syncthreads();

    for (int t = 0; t < TT; ++t) {
        // ---- prefetch gate pre-activations (independent of h; latency
        //      hidden under h-staging + dot-product loop) ----
        float gxi, gxf, gxg, gxo;
        if (tid < 128) {
            const float* gxp = gxbase + (size_t)t * (BB * G4);
            gxi = __ldcs(gxp + 0 * HH);
            gxf = __ldcs(gxp + 1 * HH);
            gxg = __ldcs(gxp + 2 * HH);
            gxo = __ldcs(gxp + 3 * HH);
        }

        // ---- stage h_t into shared ----
        if (t == 0) {
            for (int i = tid; i < SMEM_H; i += 256) hsh[i] = 0.f;
        } else {
            const float4* hb = (const float4*)&d_hbuf[t & 1][0];
            for (int i = tid; i < 4096; i += 256) {
                float4 v = __ldcg(hb + i);                       // bypass stale L1
                *(float4*)&hsh[(i >> 7) * 516 + (i & 127) * 4] = v;
            }
        }
        __syncthreads();

        // ---- dot products: acc[r] = sum_{k in chunk} Wsh[rg*8+r][k] * h[lane][k]
        float acc[8];
#pragma unroll
        for (int r = 0; r < 8; ++r) acc[r] = 0.f;
        const float4* hrow = (const float4*)&hsh[lane * 516 + kbase];
#pragma unroll 4
        for (int kk = 0; kk < 32; ++kk) {
            const float4 hv = hrow[kk];
#pragma unroll
            for (int r = 0; r < 8; ++r) {
                const float4 wv = *(const float4*)&Wsh[(rg * 8 + r) * 512 + kbase + kk * 4];
                acc[r] = fmaf(hv.x, wv.x, acc[r]);
                acc[r] = fmaf(hv.y, wv.y, acc[r]);
                acc[r] = fmaf(hv.z, wv.z, acc[r]);
                acc[r] = fmaf(hv.w, wv.w, acc[r]);
            }
        }
        // conflict-free partial-sum writes: lane stride 17 (odd)
        float* pw = &psh[ks * (32 * PSTRIDE) + lane * PSTRIDE + rg * 8];
#pragma unroll
        for (int r = 0; r < 8; ++r) pw[r] = acc[r];
        __syncthreads();

        // ---- activation (threads 0..127: one (batch, unit) each) ----
        if (tid < 128) {
            const float* pr = &psh[ab * PSTRIDE + ahl * 4];
            float pi = 0.f, pf = 0.f, pg = 0.f, po = 0.f;
#pragma unroll
            for (int q = 0; q < 4; ++q) {
                const float* p = pr + q * (32 * PSTRIDE);
                pi += p[0]; pf += p[1]; pg += p[2]; po += p[3];
            }
            pi += gxi; pf += gxf; pg += gxg; po += gxo;
            const float ig = fast_sigmoid(pi);
            const float fg = fast_sigmoid(pf);
            const float gg = fast_tanh(pg);
            const float og = fast_sigmoid(po);
            c_reg = fg * c_reg + ig * gg;
            const float h = og * fast_tanh(c_reg);
            __stcg(&d_hbuf[(t + 1) & 1][ab * HH + hid], h);
            if (store_y) __stcs(&d_y0[((size_t)t * BB + ab) * HH + hid], h);
            if (t == TT - 1) {
                out_h[ab * HH + hid] = h;
                out_c[ab * HH + hid] = c_reg;
            }
        }
        if (t != TT - 1) grid_barrier((unsigned int)(t + 1) * NBLK);
    }
}

// ---------------- launch ----------------------------------------------------
extern "C" void kernel_launch(void* const* d_in, const int* in_sizes, int n_in,
                              void* d_out, int out_size) {
    (void)in_sizes; (void)n_in; (void)out_size;
    const float* x    = (const float*)d_in[0];   // [32][512][512]
    const float* W_ih = (const float*)d_in[1];   // [2][2048][512]
    const float* W_hh = (const float*)d_in[2];   // [2][2048][512]
    const float* b_ih = (const float*)d_in[3];   // [2][2048]
    const float* b_hh = (const float*)d_in[4];   // [2][2048]
    float* out = (float*)d_out;                  // h_n [2][32][512] then c_n [2][32][512]

    cudaFuncSetAttribute(lstm_rec, cudaFuncAttributeMaxDynamicSharedMemorySize,
                         SMEM_REC_BYTES);

    const dim3 ggrid(16, 128);   // N tiles x M tiles
    const size_t wstride = (size_t)G4 * HH;      // per-layer weight stride
    const int LBH = NLAYER * BB * HH;            // 32768: offset of c_n block

    // layer 0
    gemm_gx<0><<<ggrid, 256>>>(x, W_ih, b_ih, b_hh);
    lstm_rec<<<NBLK, 256, SMEM_REC_BYTES>>>(W_hh, 1,
                                            out + 0 * BB * HH,
                                            out + LBH + 0 * BB * HH);
    // layer 1 (input = d_y0, consumed inside gemm_gx<1>)
    gemm_gx<1><<<ggrid, 256>>>(nullptr, W_ih + wstride, b_ih + G4, b_hh + G4);
    lstm_rec<<<NBLK, 256, SMEM_REC_BYTES>>>(W_hh + wstride, 0,
                                            out + 1 * BB * HH,
                                            out + LBH + 1 * BB * HH);
}